// round 1
// baseline (speedup 1.0000x reference)
#include <cuda_runtime.h>
#include <cuda_bf16.h>
#include <math.h>

// ---------------- problem constants ----------------
constexpr int B_  = 2;
constexpr int C_  = 64;
constexpr int H_  = 256;
constexpr int W_  = 1216;
constexpr int HW_ = H_ * W_;        // 311296
constexpr int NP  = B_ * HW_;       // 622592
constexpr int NCH = 78;             // 24 aff7 + 16 aff5 + 8 aff3 + 6*4 att + 6 mask
constexpr int ITERS = 6;

// scratch plane layout (each plane = NP floats)
// 0..47   aff (aff7:0-23, aff5:24-39, aff3:40-47)
// 48..53  att7 (sigmoided)   54..59 att5   60..65 att3   66..71 att1
// 72..77  mask (sigmoid * valid)
// 78 SA7, 79 SA5, 80 SA3 (sum |aff|)
// 81 T7,  82 T5,  83 T3  (sum aff)
// 84 A7, 85 A5, 86 A3, 87 BASE
// 88,89 dt ping-pong
constexpr int NPLANES = 90;

__device__ float g_scratch[(size_t)NPLANES * NP];
__device__ float g_wpack[NCH * 576];
__device__ float g_bpack[NCH];

__device__ __forceinline__ float sigf(float x) { return 1.0f / (1.0f + expf(-x)); }

// ---------------- weight packing: fold scale into weights ----------------
__global__ void pack_weights(
    const float* __restrict__ w7,  const float* __restrict__ s7,  const float* __restrict__ b7,
    const float* __restrict__ w5,  const float* __restrict__ s5,  const float* __restrict__ b5,
    const float* __restrict__ w3,  const float* __restrict__ s3,  const float* __restrict__ b3,
    const float* __restrict__ wa7, const float* __restrict__ sa7, const float* __restrict__ ba7,
    const float* __restrict__ wa5, const float* __restrict__ sa5, const float* __restrict__ ba5,
    const float* __restrict__ wa3, const float* __restrict__ sa3, const float* __restrict__ ba3,
    const float* __restrict__ wa1, const float* __restrict__ sa1, const float* __restrict__ ba1,
    const float* __restrict__ wm,  const float* __restrict__ sm,  const float* __restrict__ bm)
{
    int idx = blockIdx.x * blockDim.x + threadIdx.x;
    if (idx >= NCH * 576) return;
    int ch = idx / 576;
    int e  = idx - ch * 576;
    const float *w, *s, *b; int lc;
    if      (ch < 24) { w = w7;  s = s7;  b = b7;  lc = ch;      }
    else if (ch < 40) { w = w5;  s = s5;  b = b5;  lc = ch - 24; }
    else if (ch < 48) { w = w3;  s = s3;  b = b3;  lc = ch - 40; }
    else if (ch < 54) { w = wa7; s = sa7; b = ba7; lc = ch - 48; }
    else if (ch < 60) { w = wa5; s = sa5; b = ba5; lc = ch - 54; }
    else if (ch < 66) { w = wa3; s = sa3; b = ba3; lc = ch - 60; }
    else if (ch < 72) { w = wa1; s = sa1; b = ba1; lc = ch - 66; }
    else              { w = wm;  s = sm;  b = bm;  lc = ch - 72; }
    g_wpack[idx] = w[lc * 576 + e] * s[lc];
    if (e == 0) g_bpack[ch] = b[lc];
}

// ---------------- fused 78-channel 3x3 conv + BN + activations + reductions ----------------
// tile: 32 (x) * 16 (y), 256 threads, each thread computes 2 pixels (rows tz, tz+8)
// smem: feature tile [64][18][34] + weight chunk [13][576]
constexpr int FELEMS = 64 * 18 * 34;      // 39168
constexpr int WELEMS = 13 * 576;          // 7488
constexpr int CONV_SMEM_BYTES = (FELEMS + WELEMS) * 4;  // 186624

__global__ void __launch_bounds__(256, 1) conv_kernel(
    const float* __restrict__ feat, const float* __restrict__ d00)
{
    extern __shared__ float smem[];
    float* wsh = smem + FELEMS;

    const int tx = threadIdx.x & 31;
    const int tz = threadIdx.x >> 5;
    const int x0 = blockIdx.x * 32;
    const int y0 = blockIdx.y * 16;
    const int bb = blockIdx.z;

    // load feature tile with zero halo
    for (int idx = threadIdx.x; idx < FELEMS; idx += 256) {
        int ci = idx / (18 * 34);
        int r  = idx - ci * (18 * 34);
        int yy = r / 34;
        int xx = r - yy * 34;
        int gy = y0 - 1 + yy;
        int gx = x0 - 1 + xx;
        float v = 0.0f;
        if (gy >= 0 && gy < H_ && gx >= 0 && gx < W_)
            v = __ldg(&feat[((size_t)(bb * 64 + ci) * H_ + gy) * W_ + gx]);
        smem[idx] = v;
    }

    const int px  = x0 + tx;
    const int py0 = y0 + tz;
    const int p0  = bb * HW_ + py0 * W_ + px;
    const int p1  = p0 + 8 * W_;

    const float vld0 = (d00[p0] > 0.0f) ? 1.0f : 0.0f;
    const float vld1 = (d00[p1] > 0.0f) ? 1.0f : 0.0f;

    float sA7_0 = 0.f, sA5_0 = 0.f, sA3_0 = 0.f, tT7_0 = 0.f, tT5_0 = 0.f, tT3_0 = 0.f;
    float sA7_1 = 0.f, sA5_1 = 0.f, sA3_1 = 0.f, tT7_1 = 0.f, tT5_1 = 0.f, tT3_1 = 0.f;

    const float* frow = smem + tz * 34 + tx;

    #pragma unroll 1
    for (int chunk = 0; chunk < 6; ++chunk) {
        __syncthreads();
        for (int idx = threadIdx.x; idx < WELEMS; idx += 256)
            wsh[idx] = __ldg(&g_wpack[chunk * WELEMS + idx]);
        __syncthreads();

        float acc0[13], acc1[13];
        #pragma unroll
        for (int r = 0; r < 13; ++r) { acc0[r] = 0.f; acc1[r] = 0.f; }

        #pragma unroll 2
        for (int ci = 0; ci < 64; ++ci) {
            const float* fci = frow + ci * (18 * 34);
            const float* wci = wsh + ci * 9;
            #pragma unroll
            for (int ky = 0; ky < 3; ++ky) {
                const float fa0 = fci[ky * 34 + 0];
                const float fa1 = fci[ky * 34 + 1];
                const float fa2 = fci[ky * 34 + 2];
                const float fb0 = fci[(8 + ky) * 34 + 0];
                const float fb1 = fci[(8 + ky) * 34 + 1];
                const float fb2 = fci[(8 + ky) * 34 + 2];
                #pragma unroll
                for (int r = 0; r < 13; ++r) {
                    const float w0 = wci[r * 576 + ky * 3 + 0];
                    const float w1 = wci[r * 576 + ky * 3 + 1];
                    const float w2 = wci[r * 576 + ky * 3 + 2];
                    acc0[r] = fmaf(w0, fa0, acc0[r]);
                    acc0[r] = fmaf(w1, fa1, acc0[r]);
                    acc0[r] = fmaf(w2, fa2, acc0[r]);
                    acc1[r] = fmaf(w0, fb0, acc1[r]);
                    acc1[r] = fmaf(w1, fb1, acc1[r]);
                    acc1[r] = fmaf(w2, fb2, acc1[r]);
                }
            }
        }

        // epilogue for this channel chunk
        #pragma unroll
        for (int r = 0; r < 13; ++r) {
            const int ch = chunk * 13 + r;
            const float bias = __ldg(&g_bpack[ch]);
            float v0 = acc0[r] + bias;
            float v1 = acc1[r] + bias;
            if (ch >= 48) { v0 = sigf(v0); v1 = sigf(v1); }
            if (ch >= 72) { v0 *= vld0;    v1 *= vld1;    }
            if (ch < 24)      { sA7_0 += fabsf(v0); tT7_0 += v0; sA7_1 += fabsf(v1); tT7_1 += v1; }
            else if (ch < 40) { sA5_0 += fabsf(v0); tT5_0 += v0; sA5_1 += fabsf(v1); tT5_1 += v1; }
            else if (ch < 48) { sA3_0 += fabsf(v0); tT3_0 += v0; sA3_1 += fabsf(v1); tT3_1 += v1; }
            g_scratch[(size_t)ch * NP + p0] = v0;
            g_scratch[(size_t)ch * NP + p1] = v1;
        }
    }

    g_scratch[(size_t)78 * NP + p0] = sA7_0;  g_scratch[(size_t)78 * NP + p1] = sA7_1;
    g_scratch[(size_t)79 * NP + p0] = sA5_0;  g_scratch[(size_t)79 * NP + p1] = sA5_1;
    g_scratch[(size_t)80 * NP + p0] = sA3_0;  g_scratch[(size_t)80 * NP + p1] = sA3_1;
    g_scratch[(size_t)81 * NP + p0] = tT7_0;  g_scratch[(size_t)81 * NP + p1] = tT7_1;
    g_scratch[(size_t)82 * NP + p0] = tT5_0;  g_scratch[(size_t)82 * NP + p1] = tT5_1;
    g_scratch[(size_t)83 * NP + p0] = tT3_0;  g_scratch[(size_t)83 * NP + p1] = tT3_1;
}

// ---------------- per-iteration pointwise prep ----------------
// denom = att7*SA7 + att5*SA5 + att3*SA3 + att1   (all positive)
// sumg  = invd * (att7*T7 + att5*T5 + att3*T3 + att1)
// A_g   = att_g * invd * dt ; BASE = (1-sumg)*d0 + att1*invd*dt (center tap folded in)
__global__ void iter_a(const float* __restrict__ dt, const float* __restrict__ d0, int it)
{
    int p = blockIdx.x * 256 + threadIdx.x;
    if (p >= NP) return;
    const float* S = g_scratch;
    float a7 = S[(size_t)(48 + it) * NP + p];
    float a5 = S[(size_t)(54 + it) * NP + p];
    float a3 = S[(size_t)(60 + it) * NP + p];
    float a1 = S[(size_t)(66 + it) * NP + p];
    float denom = fmaf(a7, S[(size_t)78 * NP + p],
                  fmaf(a5, S[(size_t)79 * NP + p],
                  fmaf(a3, S[(size_t)80 * NP + p], a1)));
    float invd = 1.0f / denom;
    float sumg = invd * fmaf(a7, S[(size_t)81 * NP + p],
                        fmaf(a5, S[(size_t)82 * NP + p],
                        fmaf(a3, S[(size_t)83 * NP + p], a1)));
    float m = invd * dt[p];
    g_scratch[(size_t)84 * NP + p] = a7 * m;
    g_scratch[(size_t)85 * NP + p] = a5 * m;
    g_scratch[(size_t)86 * NP + p] = a3 * m;
    g_scratch[(size_t)87 * NP + p] = (1.0f - sumg) * d0[p] + a1 * m;
}

// ---------------- per-iteration 48-tap gather ----------------
// tap tables: offsets (dy,dx)=(3-i,3-j); plane index = group base + channel
__device__ __constant__ const int G7DY[24] = {3,3,3,3,3,3,3, 2,2, 1,1, 0,0, -1,-1, -2,-2, -3,-3,-3,-3,-3,-3,-3};
__device__ __constant__ const int G7DX[24] = {3,2,1,0,-1,-2,-3, 3,-3, 3,-3, 3,-3, 3,-3, 3,-3, 3,2,1,0,-1,-2,-3};
__device__ __constant__ const int G5DY[16] = {2,2,2,2,2, 1,1, 0,0, -1,-1, -2,-2,-2,-2,-2};
__device__ __constant__ const int G5DX[16] = {2,1,0,-1,-2, 2,-2, 2,-2, 2,-2, 2,1,0,-1,-2};
__device__ __constant__ const int G3DY[8]  = {1,1,1, 0,0, -1,-1,-1};
__device__ __constant__ const int G3DX[8]  = {1,0,-1, 1,-1, 1,0,-1};

__global__ void iter_b(const float* __restrict__ d00, float* __restrict__ out, int it)
{
    int p = blockIdx.x * 256 + threadIdx.x;
    if (p >= NP) return;
    unsigned up = (unsigned)p;
    int b = up / (unsigned)HW_;
    unsigned r = up - (unsigned)b * HW_;
    int y = r / (unsigned)W_;
    int x = r - (unsigned)y * W_;

    const float* S = g_scratch;
    const float* A7 = S + (size_t)84 * NP;
    const float* A5 = S + (size_t)85 * NP;
    const float* A3 = S + (size_t)86 * NP;

    float acc = S[(size_t)87 * NP + p];

    #pragma unroll
    for (int t = 0; t < 24; ++t) {
        const int dy = G7DY[t], dx = G7DX[t];
        if ((unsigned)(y + dy) < (unsigned)H_ && (unsigned)(x + dx) < (unsigned)W_) {
            int q = p + dy * W_ + dx;
            acc = fmaf(S[(size_t)t * NP + q], A7[q], acc);
        }
    }
    #pragma unroll
    for (int t = 0; t < 16; ++t) {
        const int dy = G5DY[t], dx = G5DX[t];
        if ((unsigned)(y + dy) < (unsigned)H_ && (unsigned)(x + dx) < (unsigned)W_) {
            int q = p + dy * W_ + dx;
            acc = fmaf(S[(size_t)(24 + t) * NP + q], A5[q], acc);
        }
    }
    #pragma unroll
    for (int t = 0; t < 8; ++t) {
        const int dy = G3DY[t], dx = G3DX[t];
        if ((unsigned)(y + dy) < (unsigned)H_ && (unsigned)(x + dx) < (unsigned)W_) {
            int q = p + dy * W_ + dx;
            acc = fmaf(S[(size_t)(40 + t) * NP + q], A3[q], acc);
        }
    }

    float mask = S[(size_t)(72 + it) * NP + p];
    out[p] = mask * d00[p] + (1.0f - mask) * acc;
}

// ---------------- launch ----------------
extern "C" void kernel_launch(void* const* d_in, const int* in_sizes, int n_in,
                              void* d_out, int out_size)
{
    const float* feat = (const float*)d_in[0];
    const float* d0   = (const float*)d_in[1];
    const float* d00  = (const float*)d_in[2];

    cudaFuncSetAttribute(conv_kernel, cudaFuncAttributeMaxDynamicSharedMemorySize,
                         CONV_SMEM_BYTES);

    pack_weights<<<(NCH * 576 + 255) / 256, 256>>>(
        (const float*)d_in[3],  (const float*)d_in[4],  (const float*)d_in[5],
        (const float*)d_in[6],  (const float*)d_in[7],  (const float*)d_in[8],
        (const float*)d_in[9],  (const float*)d_in[10], (const float*)d_in[11],
        (const float*)d_in[12], (const float*)d_in[13], (const float*)d_in[14],
        (const float*)d_in[15], (const float*)d_in[16], (const float*)d_in[17],
        (const float*)d_in[18], (const float*)d_in[19], (const float*)d_in[20],
        (const float*)d_in[21], (const float*)d_in[22], (const float*)d_in[23],
        (const float*)d_in[24], (const float*)d_in[25], (const float*)d_in[26]);

    conv_kernel<<<dim3(W_ / 32, H_ / 16, B_), 256, CONV_SMEM_BYTES>>>(feat, d00);

    void* sptr = nullptr;
    cudaGetSymbolAddress(&sptr, g_scratch);
    float* S = (float*)sptr;

    const int nblk = NP / 256;  // 2432 exact
    for (int it = 0; it < ITERS; ++it) {
        const float* dtcur = (it == 0) ? d0 : S + (size_t)(88 + ((it - 1) & 1)) * NP;
        float* dtnext = (it == ITERS - 1) ? (float*)d_out
                                          : S + (size_t)(88 + (it & 1)) * NP;
        iter_a<<<nblk, 256>>>(dtcur, d0, it);
        iter_b<<<nblk, 256>>>(d00, dtnext, it);
    }
}